// round 2
// baseline (speedup 1.0000x reference)
#include <cuda_runtime.h>
#include <cstdint>

// ---------------------------------------------------------------------------
// TernaryConv2d: out = conv2d(x, ternarize(w)*alpha) + bias
// x: [32,256,56,56] f32, w: [256,256,3,3] f32, alpha: [1], bias: [256]
// Implemented as implicit GEMM  C[256, 100352] = Wt[256,2304] @ im2col(x)
// using mma.sync.m16n8k8 TF32.  Weights are ternary (+-1/0) => exact in tf32;
// alpha is applied in the fp32 epilogue so no weight quantization error.
// ---------------------------------------------------------------------------

#define CIN   256
#define COUT  256
#define HW    56
#define BATCH 32
#define PIX   (HW*HW)          // 3136
#define NPIX  (BATCH*PIX)      // 100352
#define KTOT  (CIN*9)          // 2304
#define NW    (COUT*CIN*9)     // 589824

#define BM 128
#define BN 128
#define BK 16
#define AS_STRIDE 20           // 16 + 4 pad: conflict-free A fragment loads
#define BS_STRIDE 136          // 128 + 8 pad: conflict-free B fragment loads
#define NSTAGE (KTOT/BK)       // 144

// scratch (device globals: no allocation allowed)
__device__ float g_wt[COUT*KTOT];   // ternarized weights, K reordered k = r*256 + ci
__device__ float g_partial[256];
__device__ float g_delta;

// ------------------------- delta = 0.7 * mean|w| ---------------------------
// deterministic two-stage reduction (no float atomics)
__global__ void absmean_part(const float* __restrict__ w) {
    __shared__ float sm[256];
    int tid = threadIdx.x;
    float s = 0.f;
    int base = blockIdx.x * 256 + tid;        // 256 blocks, 9 strided elems each
#pragma unroll
    for (int k = 0; k < 9; k++) s += fabsf(w[base + k * 65536]);
    sm[tid] = s; __syncthreads();
    for (int st = 128; st > 0; st >>= 1) {
        if (tid < st) sm[tid] += sm[tid + st];
        __syncthreads();
    }
    if (tid == 0) g_partial[blockIdx.x] = sm[0];
}

__global__ void absmean_final() {
    __shared__ float sm[256];
    int tid = threadIdx.x;
    sm[tid] = g_partial[tid]; __syncthreads();
    for (int st = 128; st > 0; st >>= 1) {
        if (tid < st) sm[tid] += sm[tid + st];
        __syncthreads();
    }
    if (tid == 0) g_delta = 0.7f * sm[0] / (float)NW;
}

// --------------------- ternarize + permute K to r-major --------------------
__global__ void ternarize(const float* __restrict__ w) {
    int idx = blockIdx.x * 256 + threadIdx.x;   // 2304 blocks cover NW exactly
    float delta = g_delta;
    float v = w[idx];
    float t = (v > delta) ? 1.f : ((v < -delta) ? -1.f : 0.f);
    int co  = idx / KTOT;          // weight layout [co][ci][r] row-major
    int rem = idx - co * KTOT;
    int ci  = rem / 9;
    int rr  = rem - ci * 9;
    g_wt[co * KTOT + rr * CIN + ci] = t;   // new K index: k = rr*256 + ci
}

// ------------------------------ cp.async helpers ---------------------------
__device__ __forceinline__ void cp16(unsigned dst, const float* src) {
    asm volatile("cp.async.ca.shared.global [%0], [%1], 16;\n"
                 :: "r"(dst), "l"(src));
}
__device__ __forceinline__ void cp4z(unsigned dst, const float* src, int srcsize) {
    // srcsize = 4 (copy) or 0 (zero-fill) — im2col padding
    asm volatile("cp.async.ca.shared.global [%0], [%1], 4, %2;\n"
                 :: "r"(dst), "l"(src), "r"(srcsize));
}
__device__ __forceinline__ void cp_commit() {
    asm volatile("cp.async.commit_group;\n" ::: "memory");
}
__device__ __forceinline__ void cp_wait0() {
    asm volatile("cp.async.wait_group 0;\n" ::: "memory");
}

// ---------------------------- stage issue (gmem->smem) ---------------------
__device__ __forceinline__ void issue_stage(
    int s, float* AsBuf, float* BsBuf,
    const float* wrow,              // g_wt + (bm0+a_row)*KTOT + a_cg
    unsigned a_dst,                 // smem addr for this thread's A slot
    const float* xbase,             // x + b*CIN*PIX + nh*HW + nw
    const float* x,                 // safe fallback ptr
    int nh, int nw, unsigned b_dst, int k_half)
{
    // A: 128 rows x 16 cols, thread loads 8 contiguous floats as 2x float4
    const float* asrc = wrow + s * BK;
    cp16(a_dst,      asrc);
    cp16(a_dst + 16, asrc + 4);

    // B: stage s covers k = s*16 .. s*16+15, all with the same (dh,dw):
    //    rr = s/16, ci = (s%16)*16 + k_local
    int rr  = s >> 4;
    int ci0 = (s & 15) << 4;
    int q   = rr / 3;                 // rr in [0,9)
    int dh  = q - 1;
    int dw  = (rr - q * 3) - 1;
    bool valid = ((unsigned)(nh + dh) < (unsigned)HW) &&
                 ((unsigned)(nw + dw) < (unsigned)HW);
    int sz = valid ? 4 : 0;
    const float* src = valid ? (xbase + (ci0 + k_half * 8) * PIX + dh * HW + dw)
                             : x;
    unsigned bdst = b_dst;            // Bs + (k_half*8)*BS_STRIDE + n_local
#pragma unroll
    for (int j = 0; j < 8; j++) {
        cp4z(bdst, src, sz);
        bdst += BS_STRIDE * 4;
        src  += PIX;
    }
}

// --------------------------------- main GEMM -------------------------------
__global__ void __launch_bounds__(256)
conv_mma(const float* __restrict__ x, const float* __restrict__ alpha,
         const float* __restrict__ bias, float* __restrict__ out)
{
    __shared__ float As[2][BM * AS_STRIDE];   // 2 x 10240 B
    __shared__ float Bs[2][BK * BS_STRIDE];   // 2 x  8704 B

    int tid  = threadIdx.x;
    int lane = tid & 31;
    int warp = tid >> 5;
    int wm0 = (warp & 3) * 32;     // 4 warps along M
    int wn0 = (warp >> 2) * 64;    // 2 warps along N
    int bm0 = blockIdx.y * BM;
    int bn0 = blockIdx.x * BN;

    // ---- B-load thread mapping: fixed pixel per thread (precompute im2col) --
    int n_local = tid & 127;
    int k_half  = tid >> 7;                    // 0/1 -> k_local 0..7 / 8..15
    int n_glob  = bn0 + n_local;
    int nb   = n_glob / PIX;
    int nrem = n_glob - nb * PIX;
    int nh   = nrem / HW;
    int nw   = nrem - nh * HW;
    const float* xbase = x + (size_t)nb * (CIN * PIX) + nh * HW + nw;
    unsigned b_dst = (unsigned)__cvta_generic_to_shared(
        &Bs[0][0] + (k_half * 8) * BS_STRIDE + n_local);
    unsigned b_buf_step = (unsigned)(BK * BS_STRIDE * 4);

    // ---- A-load thread mapping: row = tid/2, 8 cols = (tid&1)*8 ----
    int a_row = tid >> 1;
    int a_cg  = (tid & 1) * 8;
    const float* wrow = g_wt + (size_t)(bm0 + a_row) * KTOT + a_cg;
    unsigned a_dst = (unsigned)__cvta_generic_to_shared(
        &As[0][0] + a_row * AS_STRIDE + a_cg);
    unsigned a_buf_step = (unsigned)(BM * AS_STRIDE * 4);

    float acc[2][8][4];
#pragma unroll
    for (int i = 0; i < 2; i++)
#pragma unroll
        for (int j = 0; j < 8; j++)
#pragma unroll
            for (int k = 0; k < 4; k++) acc[i][j][k] = 0.f;

    // prologue
    issue_stage(0, As[0], Bs[0], wrow, a_dst, xbase, x, nh, nw, b_dst, k_half);
    cp_commit();
    cp_wait0();
    __syncthreads();

    int buf = 0;
    for (int s = 0; s < NSTAGE; s++) {
        if (s + 1 < NSTAGE) {
            int nb2 = buf ^ 1;
            issue_stage(s + 1, As[nb2], Bs[nb2], wrow,
                        a_dst + nb2 * a_buf_step, xbase, x, nh, nw,
                        b_dst + nb2 * b_buf_step, k_half);
            cp_commit();
        }

        const float* Ab = As[buf];
        const float* Bb = Bs[buf];
#pragma unroll
        for (int kk = 0; kk < 2; kk++) {
            unsigned a[2][4];
#pragma unroll
            for (int mt = 0; mt < 2; mt++) {
                int r0 = wm0 + mt * 16 + (lane >> 2);
                int c0 = kk * 8 + (lane & 3);
                a[mt][0] = __float_as_uint(Ab[r0 * AS_STRIDE + c0]);
                a[mt][1] = __float_as_uint(Ab[(r0 + 8) * AS_STRIDE + c0]);
                a[mt][2] = __float_as_uint(Ab[r0 * AS_STRIDE + c0 + 4]);
                a[mt][3] = __float_as_uint(Ab[(r0 + 8) * AS_STRIDE + c0 + 4]);
            }
#pragma unroll
            for (int nt = 0; nt < 8; nt++) {
                int col = wn0 + nt * 8 + (lane >> 2);
                int kb  = kk * 8 + (lane & 3);
                float b0f = Bb[kb * BS_STRIDE + col];
                float b1f = Bb[(kb + 4) * BS_STRIDE + col];
                unsigned b0, b1;
                asm("cvt.rna.tf32.f32 %0, %1;" : "=r"(b0) : "f"(b0f));
                asm("cvt.rna.tf32.f32 %0, %1;" : "=r"(b1) : "f"(b1f));
#pragma unroll
                for (int mt = 0; mt < 2; mt++) {
                    asm volatile(
                        "mma.sync.aligned.m16n8k8.row.col.f32.tf32.tf32.f32 "
                        "{%0,%1,%2,%3}, {%4,%5,%6,%7}, {%8,%9}, {%0,%1,%2,%3};\n"
                        : "+f"(acc[mt][nt][0]), "+f"(acc[mt][nt][1]),
                          "+f"(acc[mt][nt][2]), "+f"(acc[mt][nt][3])
                        : "r"(a[mt][0]), "r"(a[mt][1]),
                          "r"(a[mt][2]), "r"(a[mt][3]),
                          "r"(b0), "r"(b1));
                }
            }
        }

        if (s + 1 < NSTAGE) {
            cp_wait0();
            __syncthreads();
            buf ^= 1;
        }
    }

    // ------------------------------ epilogue -------------------------------
    float al = alpha[0];
#pragma unroll
    for (int mt = 0; mt < 2; mt++) {
        int row = bm0 + wm0 + mt * 16 + (lane >> 2);
        float bi0 = bias[row];
        float bi8 = bias[row + 8];
#pragma unroll
        for (int nt = 0; nt < 8; nt++) {
            int n  = bn0 + wn0 + nt * 8 + (lane & 3) * 2;
            int b0i = n / PIX;       int hw0 = n - b0i * PIX;
            int n1  = n + 1;
            int b1i = n1 / PIX;      int hw1 = n1 - b1i * PIX;
            size_t o00 = ((size_t)b0i * COUT + row) * PIX + hw0;
            size_t o01 = ((size_t)b1i * COUT + row) * PIX + hw1;
            out[o00]            = al * acc[mt][nt][0] + bi0;
            out[o01]            = al * acc[mt][nt][1] + bi0;
            out[o00 + 8 * PIX]  = al * acc[mt][nt][2] + bi8;  // row+8, same b
            out[o01 + 8 * PIX]  = al * acc[mt][nt][3] + bi8;
        }
    }
}

// ------------------------------- launcher -----------------------------------
extern "C" void kernel_launch(void* const* d_in, const int* in_sizes, int n_in,
                              void* d_out, int out_size) {
    const float* x     = (const float*)d_in[0];
    const float* w     = (const float*)d_in[1];
    const float* alpha = (const float*)d_in[2];
    const float* bias  = (const float*)d_in[3];
    float* out = (float*)d_out;

    absmean_part<<<256, 256>>>(w);
    absmean_final<<<1, 256>>>();
    ternarize<<<NW / 256, 256>>>(w);

    dim3 grid(NPIX / BN, COUT / BM);   // (784, 2)
    conv_mma<<<grid, 256>>>(x, alpha, bias, out);
}

// round 4
// speedup vs baseline: 1.8987x; 1.8987x over previous
#include <cuda_runtime.h>
#include <cuda_fp16.h>
#include <cstdint>

// ---------------------------------------------------------------------------
// TernaryConv2d via implicit GEMM with mma.sync.m16n8k16.f16 (fp32 accum).
//   C[256, N'] = Wt[256,2304] @ im2col(x_h)[2304, N'],  N' = 32*56*64 (w padded)
// K order k = rr*256 + ci (constant filter tap per 16-k stage).
// x pre-quantized to fp16 in 3 dw-shifted, halo-padded copies -> producer is
// pure aligned cp.async 16B. A pre-packed in mma-fragment order -> LDS.128.
// B fragments via ldmatrix.x4.trans from swizzled smem. Ternary weights exact
// in fp16; alpha+bias applied in fp32 epilogue.
// ---------------------------------------------------------------------------

#define CIN   256
#define COUT  256
#define HW    56
#define PIX   3136
#define KTOT  2304
#define NW    (COUT*KTOT)
#define W2    64
#define H2    58
#define CHW2  (H2*W2)          // 3712
#define NPP   (HW*W2)          // 3584 padded pixels per image
#define NP    (32*NPP)         // 114688
#define XCOPY (32*CIN*CHW2)    // 30408704 halves per shifted copy

#define BM 128
#define BN 128
#define BK 16
#define NSTAGE 144
#define D 8
#define STG_A 4096
#define STG_BYTES 8192
#define SMEM_DYN (D*STG_BYTES)   // 65536

// scratch (device globals)
__device__ __half g_wth[NW];          // packed fragment-major ternary weights
__device__ __half g_xh[3*XCOPY];      // fp16 x, 3 dw-shifted halo copies
__device__ float  g_partial[256];
__device__ float  g_delta;

// ------------------------- delta = 0.7 * mean|w| ---------------------------
__global__ void absmean_part(const float* __restrict__ w) {
    __shared__ float sm[256];
    int tid = threadIdx.x;
    float s = 0.f;
    int base = blockIdx.x * 256 + tid;
#pragma unroll
    for (int k = 0; k < 9; k++) s += fabsf(w[base + k * 65536]);
    sm[tid] = s; __syncthreads();
    for (int st = 128; st > 0; st >>= 1) {
        if (tid < st) sm[tid] += sm[tid + st];
        __syncthreads();
    }
    if (tid == 0) g_partial[blockIdx.x] = sm[0];
}
__global__ void absmean_final() {
    __shared__ float sm[256];
    int tid = threadIdx.x;
    sm[tid] = g_partial[tid]; __syncthreads();
    for (int st = 128; st > 0; st >>= 1) {
        if (tid < st) sm[tid] += sm[tid + st];
        __syncthreads();
    }
    if (tid == 0) g_delta = 0.7f * sm[0] / (float)NW;
}

// -------- ternarize + pack into mma-fragment-major fp16 layout -------------
// stage s block (2048 halves): [m16(8)][lane(32)][aidx(4)][hp(2)]
__global__ void ternarize(const float* __restrict__ w) {
    int idx = blockIdx.x * 256 + threadIdx.x;
    float d = g_delta, v = w[idx];
    float t = (v > d) ? 1.f : ((v < -d) ? -1.f : 0.f);
    int co  = idx / KTOT;
    int rem = idx - co * KTOT;
    int ci  = rem / 9;
    int rr  = rem - ci * 9;
    int k   = rr * 256 + ci;
    int s   = k >> 4, kin = k & 15;
    int bm  = co >> 7, m = co & 127, m16 = m >> 4, mi = m & 15;
    int lane = ((mi & 7) << 2) | ((kin >> 1) & 3);
    int aidx = ((kin >> 3) << 1) + (mi >> 3);
    int hp   = kin & 1;
    g_wth[(((size_t)bm * NSTAGE + s) * 8 + m16) * 256 + lane * 8 + aidx * 2 + hp]
        = __float2half_rn(t);
}

// ------------- x -> fp16, 3 dw-shifted halo-padded copies -------------------
// copy dcopy at (bc=b*256+ci, h', w) holds x[b][ci][h'-1][w + dcopy - 1]
__global__ void xtoh(const float* __restrict__ x) {
    long long idx = (long long)blockIdx.x * 256 + threadIdx.x;
    int wp = (int)(idx & 63);
    long long r = idx >> 6;
    int hp = (int)(r % H2);
    long long r2 = r / H2;
    int bc    = (int)(r2 & 8191);
    int dcopy = (int)(r2 >> 13);
    int h = hp - 1;
    int w = wp + dcopy - 1;
    float v = 0.f;
    if ((unsigned)h < (unsigned)HW && (unsigned)w < (unsigned)HW)
        v = x[(long long)bc * PIX + h * HW + w];
    g_xh[idx] = __float2half_rn(v);
}

// ------------------------------ PTX helpers --------------------------------
__device__ __forceinline__ uint32_t smem_u32(const void* p) {
    uint32_t a;
    asm("{ .reg .u64 t; cvta.to.shared.u64 t, %1; cvt.u32.u64 %0, t; }"
        : "=r"(a) : "l"(p));
    return a;
}
__device__ __forceinline__ void cp16ca(uint32_t dst, const void* src) {
    asm volatile("cp.async.ca.shared.global [%0], [%1], 16;\n" :: "r"(dst), "l"(src));
}
__device__ __forceinline__ void cp16cg(uint32_t dst, const void* src) {
    asm volatile("cp.async.cg.shared.global [%0], [%1], 16;\n" :: "r"(dst), "l"(src));
}
__device__ __forceinline__ void lds128(uint32_t* a, uint32_t addr) {
    asm volatile("ld.shared.v4.b32 {%0,%1,%2,%3}, [%4];"
                 : "=r"(a[0]), "=r"(a[1]), "=r"(a[2]), "=r"(a[3]) : "r"(addr));
}
__device__ __forceinline__ void ldsm4t(uint32_t& b0, uint32_t& b1,
                                       uint32_t& b2, uint32_t& b3, uint32_t addr) {
    asm volatile("ldmatrix.sync.aligned.m8n8.x4.trans.shared.b16 {%0,%1,%2,%3}, [%4];"
                 : "=r"(b0), "=r"(b1), "=r"(b2), "=r"(b3) : "r"(addr));
}
__device__ __forceinline__ void mma16816(float* c, const uint32_t* a,
                                         uint32_t b0, uint32_t b1) {
    asm volatile(
        "mma.sync.aligned.m16n8k16.row.col.f32.f16.f16.f32 "
        "{%0,%1,%2,%3}, {%4,%5,%6,%7}, {%8,%9}, {%0,%1,%2,%3};\n"
        : "+f"(c[0]), "+f"(c[1]), "+f"(c[2]), "+f"(c[3])
        : "r"(a[0]), "r"(a[1]), "r"(a[2]), "r"(a[3]), "r"(b0), "r"(b1));
}

// --------------------------------- main GEMM -------------------------------
__global__ void __launch_bounds__(256, 2)
conv_hmma(const float* __restrict__ alpha, const float* __restrict__ bias,
          float* __restrict__ out)
{
    extern __shared__ char smem[];
    const uint32_t sb0 = smem_u32(smem);
    const int tid  = threadIdx.x;
    const int lane = tid & 31;
    const int warp = tid >> 5;
    const int bm   = blockIdx.y;
    const int bn0  = blockIdx.x * BN;

    // ---- producer constants ----
    const int kk = tid >> 4;               // k row 0..15
    const int c0 = (tid & 15) << 3;        // col chunk 0..120
    const int nc = bn0 + c0;
    const int pb = nc / NPP;
    const int ph = (nc - pb * NPP) >> 6;
    const int pw = nc & 63;
    const __half* pbase = g_xh + ((long long)pb * CIN) * CHW2 + (ph + 1) * W2 + pw;
    const uint32_t dstB = (uint32_t)((STG_A + (kk << 8) + (c0 << 1)) ^ ((kk & 7) << 4));
    const uint32_t dstA = (uint32_t)(tid << 4);
    const __half* asrc  = g_wth + (size_t)bm * (NSTAGE * 2048) + tid * 8;

    // ---- consumer constants ----
    uint32_t aoff0 = (uint32_t)((((warp & 3) * 2) << 9) + (lane << 4));
    uint32_t aoff1 = aoff0 + 512;
    const int t4 = lane >> 3, r = lane & 7;
    const int kt  = (t4 & 1) << 3;
    const int ctb = ((warp >> 2) << 6) + ((t4 >> 1) << 3);
    uint32_t boff[4];
#pragma unroll
    for (int g = 0; g < 4; g++)
        boff[g] = (uint32_t)((STG_A + ((kt + r) << 8) + ((ctb + (g << 4)) << 1))
                             ^ (r << 4));

    float acc[2][8][4];
#pragma unroll
    for (int i = 0; i < 2; i++)
#pragma unroll
        for (int j = 0; j < 8; j++)
#pragma unroll
            for (int q = 0; q < 4; q++) acc[i][j][q] = 0.f;

    auto fill = [&](int t) {
        const uint32_t sb = sb0 + (uint32_t)(t & (D - 1)) * STG_BYTES;
        cp16ca(sb + dstA, asrc + (size_t)t * 2048);
        int ci  = ((t & 15) << 4) + kk;
        int rr  = t >> 4;
        int q   = rr / 3;          // dh = q-1
        int dwp = rr - q * 3;      // dw+1 = copy index
        const __half* src = pbase + ((long long)dwp * 8192 + ci) * CHW2
                          + (q - 1) * W2;
        cp16cg(sb + dstB, src);
    };

    // ---- prologue: stages 0..D-2 in flight ----
#pragma unroll
    for (int p = 0; p < D - 1; p++) {
        fill(p);
        asm volatile("cp.async.commit_group;" ::: "memory");
    }

    // ---- main loop ----
#pragma unroll 1
    for (int s = 0; s < NSTAGE; s++) {
        asm volatile("cp.async.wait_group %0;" :: "n"(D - 2) : "memory");
        __syncthreads();                 // stage s visible; slot (s-1)%D free
        if (s + D - 1 < NSTAGE) fill(s + D - 1);
        asm volatile("cp.async.commit_group;" ::: "memory");

        const uint32_t st = sb0 + (uint32_t)(s & (D - 1)) * STG_BYTES;
        uint32_t a0[4], a1[4];
        lds128(a0, st + aoff0);
        lds128(a1, st + aoff1);
#pragma unroll
        for (int g = 0; g < 4; g++) {
            uint32_t b0, b1, b2, b3;
            ldsm4t(b0, b1, b2, b3, st + boff[g]);
            mma16816(acc[0][2 * g],     a0, b0, b1);
            mma16816(acc[1][2 * g],     a1, b0, b1);
            mma16816(acc[0][2 * g + 1], a0, b2, b3);
            mma16816(acc[1][2 * g + 1], a1, b2, b3);
        }
    }

    // ------------------------------ epilogue -------------------------------
    const float al  = alpha[0];
    const int wm0 = (warp & 3) << 5;
    const int wn0 = (warp >> 2) << 6;
#pragma unroll
    for (int mt = 0; mt < 2; mt++) {
        int co = bm * BM + wm0 + (mt << 4) + (lane >> 2);
        float bi0 = bias[co];
        float bi8 = bias[co + 8];
#pragma unroll
        for (int nt = 0; nt < 8; nt++) {
            int n = bn0 + wn0 + (nt << 3) + ((lane & 3) << 1);
            int w = n & 63;
            if (w >= HW) continue;       // dummy padded cols
            int bimg = n / NPP;
            int h = (n - bimg * NPP) >> 6;
            size_t o = ((size_t)(bimg * COUT + co)) * PIX + h * HW + w;
            float2 v0, v1;
            v0.x = al * acc[mt][nt][0] + bi0;
            v0.y = al * acc[mt][nt][1] + bi0;
            v1.x = al * acc[mt][nt][2] + bi8;
            v1.y = al * acc[mt][nt][3] + bi8;
            *reinterpret_cast<float2*>(out + o) = v0;
            *reinterpret_cast<float2*>(out + o + 8 * PIX) = v1;
        }
    }
}

// ------------------------------- launcher -----------------------------------
extern "C" void kernel_launch(void* const* d_in, const int* in_sizes, int n_in,
                              void* d_out, int out_size) {
    const float* x     = (const float*)d_in[0];
    const float* w     = (const float*)d_in[1];
    const float* alpha = (const float*)d_in[2];
    const float* bias  = (const float*)d_in[3];
    float* out = (float*)d_out;

    cudaFuncSetAttribute(conv_hmma, cudaFuncAttributeMaxDynamicSharedMemorySize,
                         SMEM_DYN);

    absmean_part<<<256, 256>>>(w);
    absmean_final<<<1, 256>>>();
    ternarize<<<NW / 256, 256>>>(w);
    xtoh<<<(3 * XCOPY) / 256, 256>>>(x);

    dim3 grid(NP / BN, COUT / BM);   // (896, 2)
    conv_hmma<<<grid, 256, SMEM_DYN>>>(alpha, bias, out);
}

// round 5
// speedup vs baseline: 2.9838x; 1.5715x over previous
#include <cuda_runtime.h>
#include <cuda_fp16.h>
#include <cstdint>

// ---------------------------------------------------------------------------
// TernaryConv2d via implicit GEMM with mma.sync.m16n8k16.f16 (fp32 accum).
//   C[256, N'] = Wt[256,2304] @ im2col(x_h)[2304, N'],  N' = 32*56*64 (w padded)
// K order k = rr*256 + ci (constant filter tap per 16-k stage).
// x pre-quantized to fp16 in 3 dw-shifted, halo-padded copies -> producer is
// pure aligned cp.async 16B. A pre-packed in mma-fragment order -> LDS.128.
// B fragments via ldmatrix.x4.trans from swizzled smem. Ternary weights exact
// in fp16; alpha+bias applied in fp32 epilogue.
// R5: xtoh rewritten: 1 thread per 8-half octet, builds all 3 shifted copies
// from one 10-float window (x read once, vector stores, no div/mod).
// ---------------------------------------------------------------------------

#define CIN   256
#define COUT  256
#define HW    56
#define PIX   3136
#define KTOT  2304
#define NW    (COUT*KTOT)
#define W2    64
#define H2    58
#define CHW2  (H2*W2)          // 3712
#define NPP   (HW*W2)          // 3584 padded pixels per image
#define NP    (32*NPP)         // 114688
#define XCOPY (32*CIN*CHW2)    // 30408704 halves per shifted copy

#define BM 128
#define BN 128
#define BK 16
#define NSTAGE 144
#define D 8
#define STG_A 4096
#define STG_BYTES 8192
#define SMEM_DYN (D*STG_BYTES)   // 65536

// scratch (device globals)
__device__ __half g_wth[NW];          // packed fragment-major ternary weights
__device__ __half g_xh[3*XCOPY];      // fp16 x, 3 dw-shifted halo copies
__device__ float  g_partial[256];
__device__ float  g_delta;

// ------------------------- delta = 0.7 * mean|w| ---------------------------
__global__ void absmean_part(const float* __restrict__ w) {
    __shared__ float sm[256];
    int tid = threadIdx.x;
    float s = 0.f;
    int base = blockIdx.x * 256 + tid;
#pragma unroll
    for (int k = 0; k < 9; k++) s += fabsf(w[base + k * 65536]);
    sm[tid] = s; __syncthreads();
    for (int st = 128; st > 0; st >>= 1) {
        if (tid < st) sm[tid] += sm[tid + st];
        __syncthreads();
    }
    if (tid == 0) g_partial[blockIdx.x] = sm[0];
}
__global__ void absmean_final() {
    __shared__ float sm[256];
    int tid = threadIdx.x;
    sm[tid] = g_partial[tid]; __syncthreads();
    for (int st = 128; st > 0; st >>= 1) {
        if (tid < st) sm[tid] += sm[tid + st];
        __syncthreads();
    }
    if (tid == 0) g_delta = 0.7f * sm[0] / (float)NW;
}

// -------- ternarize + pack into mma-fragment-major fp16 layout -------------
// stage s block (2048 halves): [m16(8)][lane(32)][aidx(4)][hp(2)]
__global__ void ternarize(const float* __restrict__ w) {
    int idx = blockIdx.x * 256 + threadIdx.x;
    float d = g_delta, v = w[idx];
    float t = (v > d) ? 1.f : ((v < -d) ? -1.f : 0.f);
    int co  = idx / KTOT;
    int rem = idx - co * KTOT;
    int ci  = rem / 9;
    int rr  = rem - ci * 9;
    int k   = rr * 256 + ci;
    int s   = k >> 4, kin = k & 15;
    int bm  = co >> 7, m = co & 127, m16 = m >> 4, mi = m & 15;
    int lane = ((mi & 7) << 2) | ((kin >> 1) & 3);
    int aidx = ((kin >> 3) << 1) + (mi >> 3);
    int hp   = kin & 1;
    g_wth[(((size_t)bm * NSTAGE + s) * 8 + m16) * 256 + lane * 8 + aidx * 2 + hp]
        = __float2half_rn(t);
}

// ------------- x -> fp16, 3 dw-shifted halo-padded copies (v2) --------------
// One thread per (bc, h', w-octet): reads the 10-float window once, emits the
// aligned 16B octet of all 3 shifted copies (prmt-repacked for dw=1).
__global__ void __launch_bounds__(512) xtoh2(const float* __restrict__ x) {
    const int bc = blockIdx.x;                 // b*256 + ci, 0..8191
    const int t  = threadIdx.x;
    if (t >= H2 * 8) return;
    const int hp = t >> 3;                     // 0..57
    const int w8 = t & 7;                      // octet within 64-wide row
    const int h  = hp - 1;
    const bool hv = (unsigned)h < (unsigned)HW;
    const float* xr = x + (size_t)bc * PIX + h * HW;

    // window covers x cols w8*8-1 .. w8*8+8
    __half hb[10];
#pragma unroll
    for (int j = 0; j < 10; j++) {
        int w = w8 * 8 - 1 + j;
        float v = (hv && (unsigned)w < (unsigned)HW) ? xr[w] : 0.f;
        hb[j] = __float2half_rn(v);
    }
    uint32_t p[5];
#pragma unroll
    for (int g = 0; g < 5; g++) {
        __half2 h2 = __halves2half2(hb[2 * g], hb[2 * g + 1]);
        p[g] = *reinterpret_cast<uint32_t*>(&h2);
    }
    uint32_t q[4];                             // dw=1 copy: pairs offset by one
#pragma unroll
    for (int g = 0; g < 4; g++)
        asm("prmt.b32 %0, %1, %2, 0x5432;" : "=r"(q[g]) : "r"(p[g]), "r"(p[g + 1]));

    const size_t base = (size_t)bc * CHW2 + hp * W2 + w8 * 8;
    uint4* o0 = reinterpret_cast<uint4*>(g_xh + base);
    uint4* o1 = reinterpret_cast<uint4*>(g_xh + base + (size_t)XCOPY);
    uint4* o2 = reinterpret_cast<uint4*>(g_xh + base + 2 * (size_t)XCOPY);
    *o0 = make_uint4(p[0], p[1], p[2], p[3]);
    *o1 = make_uint4(q[0], q[1], q[2], q[3]);
    *o2 = make_uint4(p[1], p[2], p[3], p[4]);
}

// ------------------------------ PTX helpers --------------------------------
__device__ __forceinline__ uint32_t smem_u32(const void* p) {
    uint32_t a;
    asm("{ .reg .u64 t; cvta.to.shared.u64 t, %1; cvt.u32.u64 %0, t; }"
        : "=r"(a) : "l"(p));
    return a;
}
__device__ __forceinline__ void cp16ca(uint32_t dst, const void* src) {
    asm volatile("cp.async.ca.shared.global [%0], [%1], 16;\n" :: "r"(dst), "l"(src));
}
__device__ __forceinline__ void cp16cg(uint32_t dst, const void* src) {
    asm volatile("cp.async.cg.shared.global [%0], [%1], 16;\n" :: "r"(dst), "l"(src));
}
__device__ __forceinline__ void lds128(uint32_t* a, uint32_t addr) {
    asm volatile("ld.shared.v4.b32 {%0,%1,%2,%3}, [%4];"
                 : "=r"(a[0]), "=r"(a[1]), "=r"(a[2]), "=r"(a[3]) : "r"(addr));
}
__device__ __forceinline__ void ldsm4t(uint32_t& b0, uint32_t& b1,
                                       uint32_t& b2, uint32_t& b3, uint32_t addr) {
    asm volatile("ldmatrix.sync.aligned.m8n8.x4.trans.shared.b16 {%0,%1,%2,%3}, [%4];"
                 : "=r"(b0), "=r"(b1), "=r"(b2), "=r"(b3) : "r"(addr));
}
__device__ __forceinline__ void mma16816(float* c, const uint32_t* a,
                                         uint32_t b0, uint32_t b1) {
    asm volatile(
        "mma.sync.aligned.m16n8k16.row.col.f32.f16.f16.f32 "
        "{%0,%1,%2,%3}, {%4,%5,%6,%7}, {%8,%9}, {%0,%1,%2,%3};\n"
        : "+f"(c[0]), "+f"(c[1]), "+f"(c[2]), "+f"(c[3])
        : "r"(a[0]), "r"(a[1]), "r"(a[2]), "r"(a[3]), "r"(b0), "r"(b1));
}

// --------------------------------- main GEMM -------------------------------
__global__ void __launch_bounds__(256, 2)
conv_hmma(const float* __restrict__ alpha, const float* __restrict__ bias,
          float* __restrict__ out)
{
    extern __shared__ char smem[];
    const uint32_t sb0 = smem_u32(smem);
    const int tid  = threadIdx.x;
    const int lane = tid & 31;
    const int warp = tid >> 5;
    const int bm   = blockIdx.y;
    const int bn0  = blockIdx.x * BN;

    // ---- producer constants ----
    const int kk = tid >> 4;               // k row 0..15
    const int c0 = (tid & 15) << 3;        // col chunk 0..120
    const int nc = bn0 + c0;
    const int pb = nc / NPP;
    const int ph = (nc - pb * NPP) >> 6;
    const int pw = nc & 63;
    const __half* pbase = g_xh + ((long long)pb * CIN) * CHW2 + (ph + 1) * W2 + pw;
    const uint32_t dstB = (uint32_t)((STG_A + (kk << 8) + (c0 << 1)) ^ ((kk & 7) << 4));
    const uint32_t dstA = (uint32_t)(tid << 4);
    const __half* asrc  = g_wth + (size_t)bm * (NSTAGE * 2048) + tid * 8;

    // ---- consumer constants ----
    uint32_t aoff0 = (uint32_t)((((warp & 3) * 2) << 9) + (lane << 4));
    uint32_t aoff1 = aoff0 + 512;
    const int t4 = lane >> 3, r = lane & 7;
    const int kt  = (t4 & 1) << 3;
    const int ctb = ((warp >> 2) << 6) + ((t4 >> 1) << 3);
    uint32_t boff[4];
#pragma unroll
    for (int g = 0; g < 4; g++)
        boff[g] = (uint32_t)((STG_A + ((kt + r) << 8) + ((ctb + (g << 4)) << 1))
                             ^ (r << 4));

    float acc[2][8][4];
#pragma unroll
    for (int i = 0; i < 2; i++)
#pragma unroll
        for (int j = 0; j < 8; j++)
#pragma unroll
            for (int q = 0; q < 4; q++) acc[i][j][q] = 0.f;

    auto fill = [&](int t) {
        const uint32_t sb = sb0 + (uint32_t)(t & (D - 1)) * STG_BYTES;
        cp16ca(sb + dstA, asrc + (size_t)t * 2048);
        int ci  = ((t & 15) << 4) + kk;
        int rr  = t >> 4;
        int q   = rr / 3;          // dh = q-1
        int dwp = rr - q * 3;      // dw+1 = copy index
        const __half* src = pbase + ((long long)dwp * 8192 + ci) * CHW2
                          + (q - 1) * W2;
        cp16cg(sb + dstB, src);
    };

    // ---- prologue: stages 0..D-2 in flight ----
#pragma unroll
    for (int p = 0; p < D - 1; p++) {
        fill(p);
        asm volatile("cp.async.commit_group;" ::: "memory");
    }

    // ---- main loop ----
#pragma unroll 1
    for (int s = 0; s < NSTAGE; s++) {
        asm volatile("cp.async.wait_group %0;" :: "n"(D - 2) : "memory");
        __syncthreads();                 // stage s visible; slot (s-1)%D free
        if (s + D - 1 < NSTAGE) fill(s + D - 1);
        asm volatile("cp.async.commit_group;" ::: "memory");

        const uint32_t st = sb0 + (uint32_t)(s & (D - 1)) * STG_BYTES;
        uint32_t a0[4], a1[4];
        lds128(a0, st + aoff0);
        lds128(a1, st + aoff1);
#pragma unroll
        for (int g = 0; g < 4; g++) {
            uint32_t b0, b1, b2, b3;
            ldsm4t(b0, b1, b2, b3, st + boff[g]);
            mma16816(acc[0][2 * g],     a0, b0, b1);
            mma16816(acc[1][2 * g],     a1, b0, b1);
            mma16816(acc[0][2 * g + 1], a0, b2, b3);
            mma16816(acc[1][2 * g + 1], a1, b2, b3);
        }
    }

    // ------------------------------ epilogue -------------------------------
    const float al  = alpha[0];
    const int wm0 = (warp & 3) << 5;
    const int wn0 = (warp >> 2) << 6;
#pragma unroll
    for (int mt = 0; mt < 2; mt++) {
        int co = bm * BM + wm0 + (mt << 4) + (lane >> 2);
        float bi0 = bias[co];
        float bi8 = bias[co + 8];
#pragma unroll
        for (int nt = 0; nt < 8; nt++) {
            int n = bn0 + wn0 + (nt << 3) + ((lane & 3) << 1);
            int w = n & 63;
            if (w >= HW) continue;       // dummy padded cols
            int bimg = n / NPP;
            int h = (n - bimg * NPP) >> 6;
            size_t o = ((size_t)(bimg * COUT + co)) * PIX + h * HW + w;
            float2 v0, v1;
            v0.x = al * acc[mt][nt][0] + bi0;
            v0.y = al * acc[mt][nt][1] + bi0;
            v1.x = al * acc[mt][nt][2] + bi8;
            v1.y = al * acc[mt][nt][3] + bi8;
            *reinterpret_cast<float2*>(out + o) = v0;
            *reinterpret_cast<float2*>(out + o + 8 * PIX) = v1;
        }
    }
}

// ------------------------------- launcher -----------------------------------
extern "C" void kernel_launch(void* const* d_in, const int* in_sizes, int n_in,
                              void* d_out, int out_size) {
    const float* x     = (const float*)d_in[0];
    const float* w     = (const float*)d_in[1];
    const float* alpha = (const float*)d_in[2];
    const float* bias  = (const float*)d_in[3];
    float* out = (float*)d_out;

    cudaFuncSetAttribute(conv_hmma, cudaFuncAttributeMaxDynamicSharedMemorySize,
                         SMEM_DYN);

    absmean_part<<<256, 256>>>(w);
    absmean_final<<<1, 256>>>();
    ternarize<<<NW / 256, 256>>>(w);
    xtoh2<<<8192, 512>>>(x);

    dim3 grid(NP / BN, COUT / BM);   // (896, 2)
    conv_hmma<<<grid, 256, SMEM_DYN>>>(alpha, bias, out);
}